// round 2
// baseline (speedup 1.0000x reference)
#include <cuda_runtime.h>
#include <cstddef>

#define HEADS    8
#define DIM_HEAD 64
#define QDIM     512
#define CDIM     768
#define INNER    512
#define BATCH    4
#define NQ       2048
#define NKV      2048
#define ROWS     (BATCH * NQ)   // 8192
#define SCALE    0.125f         // 64^-0.5

// Scratch (allocation-free rule: device globals)
__device__ float g_q[ROWS * INNER];
__device__ float g_k[ROWS * INNER];
__device__ float g_v[ROWS * INNER];
__device__ float g_ao[ROWS * INNER];

// ---------------------------------------------------------------------------
// NT SGEMM: C[M,N] = scale * (A[M,K] @ B[N,K]^T) + bias[n]
// BM=BN=128, BK=16, 256 threads, 8x8 micro-tile. M%128==0, N%128==0, K%16==0.
// ---------------------------------------------------------------------------
__global__ __launch_bounds__(256, 2)
void gemm_nt(const float* __restrict__ A, const float* __restrict__ Bw,
             const float* __restrict__ bias, float* __restrict__ C,
             int M, int N, int K, float scale)
{
    __shared__ float At[16][132];
    __shared__ float Bt[16][132];

    const int tid = threadIdx.x;
    const int tx = tid & 15;          // 0..15 -> 8 cols each
    const int ty = tid >> 4;          // 0..15 -> 8 rows each
    const int mBase = blockIdx.y << 7;
    const int nBase = blockIdx.x << 7;
    const int lm  = tid >> 2;         // 0..63
    const int lk4 = (tid & 3) << 2;   // 0,4,8,12

    float acc[8][8] = {};

    for (int k0 = 0; k0 < K; k0 += 16) {
#pragma unroll
        for (int r = 0; r < 128; r += 64) {
            float4 av = *(const float4*)&A [(size_t)(mBase + lm + r) * K + k0 + lk4];
            float4 bv = *(const float4*)&Bw[(size_t)(nBase + lm + r) * K + k0 + lk4];
            At[lk4 + 0][lm + r] = av.x; At[lk4 + 1][lm + r] = av.y;
            At[lk4 + 2][lm + r] = av.z; At[lk4 + 3][lm + r] = av.w;
            Bt[lk4 + 0][lm + r] = bv.x; Bt[lk4 + 1][lm + r] = bv.y;
            Bt[lk4 + 2][lm + r] = bv.z; Bt[lk4 + 3][lm + r] = bv.w;
        }
        __syncthreads();
#pragma unroll
        for (int k = 0; k < 16; k++) {
            float4 a0 = *(const float4*)&At[k][ty * 8];
            float4 a1 = *(const float4*)&At[k][ty * 8 + 4];
            float4 b0 = *(const float4*)&Bt[k][tx * 8];
            float4 b1 = *(const float4*)&Bt[k][tx * 8 + 4];
            float a[8] = {a0.x, a0.y, a0.z, a0.w, a1.x, a1.y, a1.z, a1.w};
            float b[8] = {b0.x, b0.y, b0.z, b0.w, b1.x, b1.y, b1.z, b1.w};
#pragma unroll
            for (int i = 0; i < 8; i++)
#pragma unroll
                for (int j = 0; j < 8; j++)
                    acc[i][j] += a[i] * b[j];
        }
        __syncthreads();
    }

#pragma unroll
    for (int i = 0; i < 8; i++) {
        const int m = mBase + ty * 8 + i;
#pragma unroll
        for (int j4 = 0; j4 < 8; j4 += 4) {
            const int n = nBase + tx * 8 + j4;
            float4 o;
            o.x = acc[i][j4 + 0] * scale;
            o.y = acc[i][j4 + 1] * scale;
            o.z = acc[i][j4 + 2] * scale;
            o.w = acc[i][j4 + 3] * scale;
            if (bias) {
                o.x += bias[n + 0]; o.y += bias[n + 1];
                o.z += bias[n + 2]; o.w += bias[n + 3];
            }
            *(float4*)&C[(size_t)m * N + n] = o;
        }
    }
}

// ---------------------------------------------------------------------------
// Flash attention (fp32): one CTA = (b, h, 128-query tile), K-tiles of 64.
// Q is pre-scaled by SCALE at projection time.
// smem layout (floats):
//   Qt [64][132]  (k-major: [d][q])
//   St [64][132]  (transposed scores: [key][q])
//   Kt [64][68]   (k-major: [d][key])
//   Vs [64][68]   (natural: [key][d])
//   m_s/l_s/alpha_s [128], red [2][128]
// ---------------------------------------------------------------------------
#define ATTN_SMEM_FLOATS (64*132 + 64*132 + 64*68 + 64*68 + 3*128 + 256)
#define ATTN_SMEM_BYTES  (ATTN_SMEM_FLOATS * 4)

__global__ __launch_bounds__(256, 2)
void attn_kernel()
{
    extern __shared__ float sm[];
    float* Qt      = sm;                   // 64*132
    float* St      = Qt + 64 * 132;        // 64*132
    float* Kt      = St + 64 * 132;        // 64*68
    float* Vs      = Kt + 64 * 68;         // 64*68
    float* m_s     = Vs + 64 * 68;         // 128
    float* l_s     = m_s + 128;            // 128
    float* alpha_s = l_s + 128;            // 128
    float* red     = alpha_s + 128;        // 2*128

    const int tid = threadIdx.x;
    const int tx = tid & 15;       // 0..15 -> 4 key-cols / 4 d-cols each
    const int ty = tid >> 4;       // 0..15 -> 8 query-rows each
    const int qb = blockIdx.x << 7;    // query tile base
    const int h  = blockIdx.y;
    const int b  = blockIdx.z;

    const int row  = tid & 127;    // softmax row owned
    const int half = tid >> 7;     // which half of the 64 keys

    // init running stats
    if (tid < 128) { m_s[tid] = -1e30f; l_s[tid] = 0.f; }

    // load Q tile (128 x 64), transposed into Qt[d][q]
#pragma unroll
    for (int i = tid; i < 2048; i += 256) {
        int r = i >> 4, d4 = (i & 15) << 2;
        float4 qv = *(const float4*)&g_q[(size_t)(b * NQ + qb + r) * INNER + h * 64 + d4];
        Qt[(d4 + 0) * 132 + r] = qv.x; Qt[(d4 + 1) * 132 + r] = qv.y;
        Qt[(d4 + 2) * 132 + r] = qv.z; Qt[(d4 + 3) * 132 + r] = qv.w;
    }
    __syncthreads();

    float acc[8][4] = {};

    for (int kb = 0; kb < NKV; kb += 64) {
        // load K (transposed) and V (natural) tiles: 64 x 64 each
#pragma unroll
        for (int i = tid; i < 1024; i += 256) {
            int r = i >> 4, d4 = (i & 15) << 2;
            size_t gofs = (size_t)(b * NKV + kb + r) * INNER + h * 64 + d4;
            float4 kv = *(const float4*)&g_k[gofs];
            Kt[(d4 + 0) * 68 + r] = kv.x; Kt[(d4 + 1) * 68 + r] = kv.y;
            Kt[(d4 + 2) * 68 + r] = kv.z; Kt[(d4 + 3) * 68 + r] = kv.w;
            float4 vv = *(const float4*)&g_v[gofs];
            *(float4*)&Vs[r * 68 + d4] = vv;
        }
        __syncthreads();

        // S = Q @ K^T  (128 x 64), 8x4 per thread, inner d = 64
        float sreg[8][4] = {};
#pragma unroll 8
        for (int d = 0; d < 64; d++) {
            float4 a0 = *(const float4*)&Qt[d * 132 + ty * 8];
            float4 a1 = *(const float4*)&Qt[d * 132 + ty * 8 + 4];
            float4 b0 = *(const float4*)&Kt[d * 68 + tx * 4];
            float a[8] = {a0.x, a0.y, a0.z, a0.w, a1.x, a1.y, a1.z, a1.w};
            float bb[4] = {b0.x, b0.y, b0.z, b0.w};
#pragma unroll
            for (int i = 0; i < 8; i++)
#pragma unroll
                for (int j = 0; j < 4; j++)
                    sreg[i][j] += a[i] * bb[j];
        }
        // store transposed: St[key][query]
#pragma unroll
        for (int i = 0; i < 8; i++)
#pragma unroll
            for (int j = 0; j < 4; j++)
                St[(tx * 4 + j) * 132 + ty * 8 + i] = sreg[i][j];
        __syncthreads();

        // --- online softmax over this 64-key tile ---
        float pm = -1e30f;
#pragma unroll
        for (int j = half * 32; j < half * 32 + 32; j++)
            pm = fmaxf(pm, St[j * 132 + row]);
        red[half * 128 + row] = pm;
        __syncthreads();

        if (tid < 128) {
            float mn = fmaxf(m_s[row], fmaxf(red[row], red[128 + row]));
            alpha_s[row] = __expf(m_s[row] - mn);
            m_s[row] = mn;
        }
        __syncthreads();

        {
            float mn = m_s[row];
            float ps = 0.f;
#pragma unroll
            for (int j = half * 32; j < half * 32 + 32; j++) {
                float p = __expf(St[j * 132 + row] - mn);
                St[j * 132 + row] = p;
                ps += p;
            }
            red[half * 128 + row] = ps;
        }
        __syncthreads();
        if (tid < 128)
            l_s[row] = l_s[row] * alpha_s[row] + red[row] + red[128 + row];

        // rescale accumulator and add P @ V  (inner j = 64 keys)
#pragma unroll
        for (int i = 0; i < 8; i++) {
            float al = alpha_s[ty * 8 + i];
#pragma unroll
            for (int j = 0; j < 4; j++) acc[i][j] *= al;
        }
#pragma unroll 8
        for (int j0 = 0; j0 < 64; j0++) {
            float4 a0 = *(const float4*)&St[j0 * 132 + ty * 8];
            float4 a1 = *(const float4*)&St[j0 * 132 + ty * 8 + 4];
            float4 b0 = *(const float4*)&Vs[j0 * 68 + tx * 4];
            float a[8] = {a0.x, a0.y, a0.z, a0.w, a1.x, a1.y, a1.z, a1.w};
            float bb[4] = {b0.x, b0.y, b0.z, b0.w};
#pragma unroll
            for (int i = 0; i < 8; i++)
#pragma unroll
                for (int j = 0; j < 4; j++)
                    acc[i][j] += a[i] * bb[j];
        }
        __syncthreads();   // protects Kt/Vs/St for next tile; orders l_s
    }

    // normalize and write out: g_ao[(b*NQ+q)][h*64+d]
#pragma unroll
    for (int i = 0; i < 8; i++) {
        float inv_l = 1.f / l_s[ty * 8 + i];
        float4 o;
        o.x = acc[i][0] * inv_l; o.y = acc[i][1] * inv_l;
        o.z = acc[i][2] * inv_l; o.w = acc[i][3] * inv_l;
        *(float4*)&g_ao[(size_t)(b * NQ + qb + ty * 8 + i) * INNER + h * 64 + tx * 4] = o;
    }
}

// ---------------------------------------------------------------------------
extern "C" void kernel_launch(void* const* d_in, const int* in_sizes, int n_in,
                              void* d_out, int out_size)
{
    const float* x   = (const float*)d_in[0];  // [4,2048,512]
    const float* ctx = (const float*)d_in[1];  // [4,2048,768]
    const float* Wq  = (const float*)d_in[2];  // [512,512]
    const float* Wk  = (const float*)d_in[3];  // [512,768]
    const float* Wv  = (const float*)d_in[4];  // [512,768]
    const float* Wo  = (const float*)d_in[5];  // [512,512]
    const float* bo  = (const float*)d_in[6];  // [512]
    float* out = (float*)d_out;

    float *qp, *kp, *vp, *ap;
    cudaGetSymbolAddress((void**)&qp, g_q);
    cudaGetSymbolAddress((void**)&kp, g_k);
    cudaGetSymbolAddress((void**)&vp, g_v);
    cudaGetSymbolAddress((void**)&ap, g_ao);

    dim3 gProj(INNER / 128, ROWS / 128);   // (4, 64)

    // Q = x @ Wq^T * SCALE ; K = ctx @ Wk^T ; V = ctx @ Wv^T
    gemm_nt<<<gProj, 256>>>(x,   Wq, nullptr, qp, ROWS, INNER, QDIM, SCALE);
    gemm_nt<<<gProj, 256>>>(ctx, Wk, nullptr, kp, ROWS, INNER, CDIM, 1.0f);
    gemm_nt<<<gProj, 256>>>(ctx, Wv, nullptr, vp, ROWS, INNER, CDIM, 1.0f);

    cudaFuncSetAttribute(attn_kernel,
                         cudaFuncAttributeMaxDynamicSharedMemorySize,
                         ATTN_SMEM_BYTES);
    attn_kernel<<<dim3(NQ / 128, HEADS, BATCH), 256, ATTN_SMEM_BYTES>>>();

    // out = attn_out @ Wo^T + bo
    gemm_nt<<<dim3(QDIM / 128, ROWS / 128), 256>>>(ap, Wo, bo, out,
                                                   ROWS, QDIM, INNER, 1.0f);
}

// round 7
// speedup vs baseline: 1.0644x; 1.0644x over previous
#include <cuda_runtime.h>
#include <cstdint>
#include <cstddef>

#define HEADS    8
#define DIM_HEAD 64
#define QDIM     512
#define CDIM     768
#define INNER    512
#define BATCH    4
#define NQ       2048
#define NKV      2048
#define ROWS     (BATCH * NQ)   // 8192
#define SCALE    0.125f         // 64^-0.5

// Scratch (allocation-free rule: device globals)
__device__ float g_q[ROWS * INNER];
__device__ float g_k[ROWS * INNER];
__device__ float g_v[ROWS * INNER];
__device__ float g_ao[ROWS * INNER];

// ===========================================================================
// Warp-MMA tf32 helpers (baseline PTX, no sm_103a-only instructions)
// ===========================================================================
__device__ __forceinline__ uint32_t tf32_bits(float x) {
    uint32_t r;
    asm("cvt.rna.tf32.f32 %0, %1;" : "=r"(r) : "f"(x));
    return r;
}

// split x into hi (tf32) + lo (tf32 of remainder); both returned as b32 bits
__device__ __forceinline__ void tf32_split(float x, uint32_t& hi, uint32_t& lo) {
    hi = tf32_bits(x);
    lo = tf32_bits(x - __uint_as_float(hi));
}

#define MMA_TF32(d, a, b)                                                     \
    asm volatile(                                                             \
        "mma.sync.aligned.m16n8k8.row.col.f32.tf32.tf32.f32 "                 \
        "{%0,%1,%2,%3}, {%4,%5,%6,%7}, {%8,%9}, {%0,%1,%2,%3};"               \
        : "+f"((d)[0]), "+f"((d)[1]), "+f"((d)[2]), "+f"((d)[3])              \
        : "r"((a)[0]), "r"((a)[1]), "r"((a)[2]), "r"((a)[3]),                 \
          "r"((b)[0]), "r"((b)[1]))

// ===========================================================================
// 3xTF32 NT GEMM on tensor cores: C[M,ldc] = scale*(A[M,K] @ B[N,K]^T) + bias
// CTA tile 128x128, BK=16, 256 threads = 8 warps (2x4), warp tile 64x32.
// smem As[m][k], Bs[n][k] with pad 20 -> conflict-free fragment reads.
// ===========================================================================
__global__ __launch_bounds__(256)
void gemm_mma(const float* __restrict__ A, const float* __restrict__ Bw,
              const float* __restrict__ bias, float* __restrict__ C,
              int M, int ldc, int K, float scale)
{
    __shared__ float As[128][20];
    __shared__ float Bs[128][20];

    const int tid    = threadIdx.x;
    const int warp   = tid >> 5;
    const int lane   = tid & 31;
    const int gid    = lane >> 2;       // 0..7
    const int tig    = lane & 3;        // 0..3
    const int warp_m = warp & 1;        // 0..1 -> 64 rows
    const int warp_n = warp >> 1;       // 0..3 -> 32 cols
    const int mBase  = blockIdx.y << 7;
    const int nBase  = blockIdx.x << 7;

    const int lrow = tid >> 2;          // 0..63
    const int lk4  = (tid & 3) << 2;    // 0,4,8,12

    float acc[4][4][4] = {};            // [mi][ni][reg]

    for (int k0 = 0; k0 < K; k0 += 16) {
#pragma unroll
        for (int r = 0; r < 128; r += 64) {
            float4 av = *(const float4*)&A [(size_t)(mBase + lrow + r) * K + k0 + lk4];
            float4 bv = *(const float4*)&Bw[(size_t)(nBase + lrow + r) * K + k0 + lk4];
            *(float4*)&As[lrow + r][lk4] = av;
            *(float4*)&Bs[lrow + r][lk4] = bv;
        }
        __syncthreads();

#pragma unroll
        for (int ks = 0; ks < 16; ks += 8) {
            // B fragments for the 4 n-subtiles (hi/lo)
            uint32_t bh[4][2], bl[4][2];
#pragma unroll
            for (int ni = 0; ni < 4; ni++) {
                const int col = warp_n * 32 + ni * 8 + gid;
                tf32_split(Bs[col][ks + tig],     bh[ni][0], bl[ni][0]);
                tf32_split(Bs[col][ks + tig + 4], bh[ni][1], bl[ni][1]);
            }
#pragma unroll
            for (int mi = 0; mi < 4; mi++) {
                const int row = warp_m * 64 + mi * 16 + gid;
                uint32_t ah[4], al[4];
                tf32_split(As[row][ks + tig],         ah[0], al[0]);
                tf32_split(As[row + 8][ks + tig],     ah[1], al[1]);
                tf32_split(As[row][ks + tig + 4],     ah[2], al[2]);
                tf32_split(As[row + 8][ks + tig + 4], ah[3], al[3]);
#pragma unroll
                for (int ni = 0; ni < 4; ni++) {
                    MMA_TF32(acc[mi][ni], ah, bh[ni]);
                    MMA_TF32(acc[mi][ni], ah, bl[ni]);
                    MMA_TF32(acc[mi][ni], al, bh[ni]);
                }
            }
        }
        __syncthreads();
    }

    // Epilogue: c0=(gid, tig*2), c1=(gid, tig*2+1), c2/c3 same cols at row+8
#pragma unroll
    for (int mi = 0; mi < 4; mi++) {
        const int row0 = mBase + warp_m * 64 + mi * 16 + gid;
#pragma unroll
        for (int ni = 0; ni < 4; ni++) {
            const int col = nBase + warp_n * 32 + ni * 8 + tig * 2;
            float b0 = 0.f, b1 = 0.f;
            if (bias) { b0 = bias[col]; b1 = bias[col + 1]; }
            float2 o0, o1;
            o0.x = acc[mi][ni][0] * scale + b0;
            o0.y = acc[mi][ni][1] * scale + b1;
            o1.x = acc[mi][ni][2] * scale + b0;
            o1.y = acc[mi][ni][3] * scale + b1;
            *(float2*)&C[(size_t)row0 * ldc + col]       = o0;
            *(float2*)&C[(size_t)(row0 + 8) * ldc + col] = o1;
        }
    }
}

// ---------------------------------------------------------------------------
// Flash attention (fp32 SIMT) — unchanged from passing round.
// ---------------------------------------------------------------------------
#define ATTN_SMEM_FLOATS (64*132 + 64*132 + 64*68 + 64*68 + 3*128 + 256)
#define ATTN_SMEM_BYTES  (ATTN_SMEM_FLOATS * 4)

__global__ __launch_bounds__(256, 2)
void attn_kernel()
{
    extern __shared__ float smf[];
    float* Qt      = smf;
    float* St      = Qt + 64 * 132;
    float* Kt      = St + 64 * 132;
    float* Vs      = Kt + 64 * 68;
    float* m_s     = Vs + 64 * 68;
    float* l_s     = m_s + 128;
    float* alpha_s = l_s + 128;
    float* red     = alpha_s + 128;

    const int tid = threadIdx.x;
    const int tx = tid & 15;
    const int ty = tid >> 4;
    const int qb = blockIdx.x << 7;
    const int h  = blockIdx.y;
    const int b  = blockIdx.z;

    const int row  = tid & 127;
    const int half = tid >> 7;

    if (tid < 128) { m_s[tid] = -1e30f; l_s[tid] = 0.f; }

#pragma unroll
    for (int i = tid; i < 2048; i += 256) {
        int r = i >> 4, d4 = (i & 15) << 2;
        float4 qv = *(const float4*)&g_q[(size_t)(b * NQ + qb + r) * INNER + h * 64 + d4];
        Qt[(d4 + 0) * 132 + r] = qv.x; Qt[(d4 + 1) * 132 + r] = qv.y;
        Qt[(d4 + 2) * 132 + r] = qv.z; Qt[(d4 + 3) * 132 + r] = qv.w;
    }
    __syncthreads();

    float acc[8][4] = {};

    for (int kb = 0; kb < NKV; kb += 64) {
#pragma unroll
        for (int i = tid; i < 1024; i += 256) {
            int r = i >> 4, d4 = (i & 15) << 2;
            size_t gofs = (size_t)(b * NKV + kb + r) * INNER + h * 64 + d4;
            float4 kv = *(const float4*)&g_k[gofs];
            Kt[(d4 + 0) * 68 + r] = kv.x; Kt[(d4 + 1) * 68 + r] = kv.y;
            Kt[(d4 + 2) * 68 + r] = kv.z; Kt[(d4 + 3) * 68 + r] = kv.w;
            float4 vv = *(const float4*)&g_v[gofs];
            *(float4*)&Vs[r * 68 + d4] = vv;
        }
        __syncthreads();

        float sreg[8][4] = {};
#pragma unroll 8
        for (int d = 0; d < 64; d++) {
            float4 a0 = *(const float4*)&Qt[d * 132 + ty * 8];
            float4 a1 = *(const float4*)&Qt[d * 132 + ty * 8 + 4];
            float4 b0 = *(const float4*)&Kt[d * 68 + tx * 4];
            float a[8] = {a0.x, a0.y, a0.z, a0.w, a1.x, a1.y, a1.z, a1.w};
            float bb[4] = {b0.x, b0.y, b0.z, b0.w};
#pragma unroll
            for (int i = 0; i < 8; i++)
#pragma unroll
                for (int j = 0; j < 4; j++)
                    sreg[i][j] += a[i] * bb[j];
        }
#pragma unroll
        for (int i = 0; i < 8; i++)
#pragma unroll
            for (int j = 0; j < 4; j++)
                St[(tx * 4 + j) * 132 + ty * 8 + i] = sreg[i][j];
        __syncthreads();

        float pm = -1e30f;
#pragma unroll
        for (int j = half * 32; j < half * 32 + 32; j++)
            pm = fmaxf(pm, St[j * 132 + row]);
        red[half * 128 + row] = pm;
        __syncthreads();

        if (tid < 128) {
            float mn = fmaxf(m_s[row], fmaxf(red[row], red[128 + row]));
            alpha_s[row] = __expf(m_s[row] - mn);
            m_s[row] = mn;
        }
        __syncthreads();

        {
            float mn = m_s[row];
            float ps = 0.f;
#pragma unroll
            for (int j = half * 32; j < half * 32 + 32; j++) {
                float p = __expf(St[j * 132 + row] - mn);
                St[j * 132 + row] = p;
                ps += p;
            }
            red[half * 128 + row] = ps;
        }
        __syncthreads();
        if (tid < 128)
            l_s[row] = l_s[row] * alpha_s[row] + red[row] + red[128 + row];

#pragma unroll
        for (int i = 0; i < 8; i++) {
            float al = alpha_s[ty * 8 + i];
#pragma unroll
            for (int j = 0; j < 4; j++) acc[i][j] *= al;
        }
#pragma unroll 8
        for (int j0 = 0; j0 < 64; j0++) {
            float4 a0 = *(const float4*)&St[j0 * 132 + ty * 8];
            float4 a1 = *(const float4*)&St[j0 * 132 + ty * 8 + 4];
            float4 b0 = *(const float4*)&Vs[j0 * 68 + tx * 4];
            float a[8] = {a0.x, a0.y, a0.z, a0.w, a1.x, a1.y, a1.z, a1.w};
            float bb[4] = {b0.x, b0.y, b0.z, b0.w};
#pragma unroll
            for (int i = 0; i < 8; i++)
#pragma unroll
                for (int j = 0; j < 4; j++)
                    acc[i][j] += a[i] * bb[j];
        }
        __syncthreads();
    }

#pragma unroll
    for (int i = 0; i < 8; i++) {
        float inv_l = 1.f / l_s[ty * 8 + i];
        float4 o;
        o.x = acc[i][0] * inv_l; o.y = acc[i][1] * inv_l;
        o.z = acc[i][2] * inv_l; o.w = acc[i][3] * inv_l;
        *(float4*)&g_ao[(size_t)(b * NQ + qb + ty * 8 + i) * INNER + h * 64 + tx * 4] = o;
    }
}

// ---------------------------------------------------------------------------
extern "C" void kernel_launch(void* const* d_in, const int* in_sizes, int n_in,
                              void* d_out, int out_size)
{
    const float* x   = (const float*)d_in[0];  // [4,2048,512]
    const float* ctx = (const float*)d_in[1];  // [4,2048,768]
    const float* Wq  = (const float*)d_in[2];  // [512,512]
    const float* Wk  = (const float*)d_in[3];  // [512,768]
    const float* Wv  = (const float*)d_in[4];  // [512,768]
    const float* Wo  = (const float*)d_in[5];  // [512,512]
    const float* bo  = (const float*)d_in[6];  // [512]
    float* out = (float*)d_out;

    float *qp, *kp, *vp, *ap;
    cudaGetSymbolAddress((void**)&qp, g_q);
    cudaGetSymbolAddress((void**)&kp, g_k);
    cudaGetSymbolAddress((void**)&vp, g_v);
    cudaGetSymbolAddress((void**)&ap, g_ao);

    dim3 gProj(INNER / 128, ROWS / 128);   // (4, 64)

    // Q = x @ Wq^T * SCALE ; K = ctx @ Wk^T ; V = ctx @ Wv^T
    gemm_mma<<<gProj, 256>>>(x,   Wq, nullptr, qp, ROWS, INNER, QDIM, SCALE);
    gemm_mma<<<gProj, 256>>>(ctx, Wk, nullptr, kp, ROWS, INNER, CDIM, 1.0f);
    gemm_mma<<<gProj, 256>>>(ctx, Wv, nullptr, vp, ROWS, INNER, CDIM, 1.0f);

    cudaFuncSetAttribute(attn_kernel,
                         cudaFuncAttributeMaxDynamicSharedMemorySize,
                         ATTN_SMEM_BYTES);
    attn_kernel<<<dim3(NQ / 128, HEADS, BATCH), 256, ATTN_SMEM_BYTES>>>();

    // out = attn_out @ Wo^T + bo
    gemm_mma<<<dim3(QDIM / 128, ROWS / 128), 256>>>(ap, Wo, bo, out,
                                                    ROWS, QDIM, INNER, 1.0f);
}

// round 8
// speedup vs baseline: 1.2298x; 1.1554x over previous
#include <cuda_runtime.h>
#include <cstdint>
#include <cstddef>

#define HEADS    8
#define DIM_HEAD 64
#define QDIM     512
#define CDIM     768
#define INNER    512
#define BATCH    4
#define NQ       2048
#define NKV      2048
#define ROWS     (BATCH * NQ)   // 8192
#define SCALE    0.125f         // 64^-0.5

// Scratch (allocation-free rule: device globals)
__device__ float g_q[ROWS * INNER];
__device__ float g_k[ROWS * INNER];
__device__ float g_v[ROWS * INNER];
__device__ float g_ao[ROWS * INNER];

// ===========================================================================
// Warp-MMA tf32 helpers (baseline PTX, no sm_103a-only instructions)
// ===========================================================================
__device__ __forceinline__ uint32_t tf32_bits(float x) {
    uint32_t r;
    asm("cvt.rna.tf32.f32 %0, %1;" : "=r"(r) : "f"(x));
    return r;
}

__device__ __forceinline__ void tf32_split(float x, uint32_t& hi, uint32_t& lo) {
    hi = tf32_bits(x);
    lo = tf32_bits(x - __uint_as_float(hi));
}

#define MMA_TF32(d, a, b)                                                     \
    asm volatile(                                                             \
        "mma.sync.aligned.m16n8k8.row.col.f32.tf32.tf32.f32 "                 \
        "{%0,%1,%2,%3}, {%4,%5,%6,%7}, {%8,%9}, {%0,%1,%2,%3};"               \
        : "+f"((d)[0]), "+f"((d)[1]), "+f"((d)[2]), "+f"((d)[3])              \
        : "r"((a)[0]), "r"((a)[1]), "r"((a)[2]), "r"((a)[3]),                 \
          "r"((b)[0]), "r"((b)[1]))

// ===========================================================================
// 3xTF32 NT GEMM: C = scale*(A @ B^T) + bias.  128x128 CTA tile, BK=16,
// 256 threads = 8 warps (2x4), warp tile 64x32.  tf32 split hoisted to the
// load stage: smem holds hi/lo tf32 bit patterns (conflict-free pad 20).
// ===========================================================================
__global__ __launch_bounds__(256)
void gemm_mma(const float* __restrict__ A, const float* __restrict__ Bw,
              const float* __restrict__ bias, float* __restrict__ C,
              int M, int ldc, int K, float scale)
{
    __shared__ uint32_t Ah[128][20], Al[128][20];
    __shared__ uint32_t Bh[128][20], Bl[128][20];

    const int tid    = threadIdx.x;
    const int warp   = tid >> 5;
    const int lane   = tid & 31;
    const int gid    = lane >> 2;       // 0..7
    const int tig    = lane & 3;        // 0..3
    const int warp_m = warp & 1;
    const int warp_n = warp >> 1;
    const int mBase  = blockIdx.y << 7;
    const int nBase  = blockIdx.x << 7;

    const int lrow = tid >> 2;          // 0..63
    const int lk4  = (tid & 3) << 2;    // 0,4,8,12

    float acc[4][4][4] = {};

    for (int k0 = 0; k0 < K; k0 += 16) {
#pragma unroll
        for (int r = 0; r < 128; r += 64) {
            float4 av = *(const float4*)&A [(size_t)(mBase + lrow + r) * K + k0 + lk4];
            float4 bv = *(const float4*)&Bw[(size_t)(nBase + lrow + r) * K + k0 + lk4];
            uint32_t h0, h1, h2, h3, l0, l1, l2, l3;
            tf32_split(av.x, h0, l0); tf32_split(av.y, h1, l1);
            tf32_split(av.z, h2, l2); tf32_split(av.w, h3, l3);
            Ah[lrow + r][lk4] = h0; Ah[lrow + r][lk4 + 1] = h1;
            Ah[lrow + r][lk4 + 2] = h2; Ah[lrow + r][lk4 + 3] = h3;
            Al[lrow + r][lk4] = l0; Al[lrow + r][lk4 + 1] = l1;
            Al[lrow + r][lk4 + 2] = l2; Al[lrow + r][lk4 + 3] = l3;
            tf32_split(bv.x, h0, l0); tf32_split(bv.y, h1, l1);
            tf32_split(bv.z, h2, l2); tf32_split(bv.w, h3, l3);
            Bh[lrow + r][lk4] = h0; Bh[lrow + r][lk4 + 1] = h1;
            Bh[lrow + r][lk4 + 2] = h2; Bh[lrow + r][lk4 + 3] = h3;
            Bl[lrow + r][lk4] = l0; Bl[lrow + r][lk4 + 1] = l1;
            Bl[lrow + r][lk4 + 2] = l2; Bl[lrow + r][lk4 + 3] = l3;
        }
        __syncthreads();

#pragma unroll
        for (int ks = 0; ks < 16; ks += 8) {
            uint32_t bh[4][2], bl[4][2];
#pragma unroll
            for (int ni = 0; ni < 4; ni++) {
                const int col = warp_n * 32 + ni * 8 + gid;
                bh[ni][0] = Bh[col][ks + tig];     bl[ni][0] = Bl[col][ks + tig];
                bh[ni][1] = Bh[col][ks + tig + 4]; bl[ni][1] = Bl[col][ks + tig + 4];
            }
#pragma unroll
            for (int mi = 0; mi < 4; mi++) {
                const int row = warp_m * 64 + mi * 16 + gid;
                uint32_t ah[4], al[4];
                ah[0] = Ah[row][ks + tig];         al[0] = Al[row][ks + tig];
                ah[1] = Ah[row + 8][ks + tig];     al[1] = Al[row + 8][ks + tig];
                ah[2] = Ah[row][ks + tig + 4];     al[2] = Al[row][ks + tig + 4];
                ah[3] = Ah[row + 8][ks + tig + 4]; al[3] = Al[row + 8][ks + tig + 4];
#pragma unroll
                for (int ni = 0; ni < 4; ni++) {
                    MMA_TF32(acc[mi][ni], ah, bh[ni]);
                    MMA_TF32(acc[mi][ni], ah, bl[ni]);
                    MMA_TF32(acc[mi][ni], al, bh[ni]);
                }
            }
        }
        __syncthreads();
    }

#pragma unroll
    for (int mi = 0; mi < 4; mi++) {
        const int row0 = mBase + warp_m * 64 + mi * 16 + gid;
#pragma unroll
        for (int ni = 0; ni < 4; ni++) {
            const int col = nBase + warp_n * 32 + ni * 8 + tig * 2;
            float b0 = 0.f, b1 = 0.f;
            if (bias) { b0 = bias[col]; b1 = bias[col + 1]; }
            float2 o0, o1;
            o0.x = acc[mi][ni][0] * scale + b0;
            o0.y = acc[mi][ni][1] * scale + b1;
            o1.x = acc[mi][ni][2] * scale + b0;
            o1.y = acc[mi][ni][3] * scale + b1;
            *(float2*)&C[(size_t)row0 * ldc + col]       = o0;
            *(float2*)&C[(size_t)(row0 + 8) * ldc + col] = o1;
        }
    }
}

// ===========================================================================
// Tensor-core flash attention (tf32 warp MMA).
// CTA = (b, h, 128 q-rows), 256 threads = 8 warps; warp owns 16 q-rows.
// KV tiles of 64. S = Q@K^T via 8x8 m16n8k8 MMAs; softmax in registers
// (bfly over 4 lanes/row); P -> per-warp smem as tf32; O += P@V.
// smem (uints): Ks[64][68], Vs[64][72], P[8][16][68]  (pre-converted tf32)
// ===========================================================================
#define A2_OFF_VS (64 * 68)
#define A2_OFF_P  (A2_OFF_VS + 64 * 72)
#define A2_SMEM_UINTS (A2_OFF_P + 8 * 16 * 68)
#define A2_SMEM_BYTES (A2_SMEM_UINTS * 4)   // 70656

__global__ __launch_bounds__(256, 2)
void attn_mma()
{
    extern __shared__ uint32_t su[];
    uint32_t* Ks = su;
    uint32_t* Vs = su + A2_OFF_VS;

    const int tid  = threadIdx.x;
    const int warp = tid >> 5;
    const int lane = tid & 31;
    const int g    = lane >> 2;     // 0..7
    const int t    = lane & 3;      // 0..3
    const int qb   = blockIdx.x << 7;
    const int h    = blockIdx.y;
    const int b    = blockIdx.z;

    uint32_t* Pm = su + A2_OFF_P + warp * (16 * 68);

    // Q fragments for this warp's 16 rows (Q pre-scaled by SCALE), tf32, held
    uint32_t qf[8][4];
    {
        const float* Qb = g_q + (size_t)(b * NQ + qb + warp * 16) * INNER + h * 64;
#pragma unroll
        for (int kc = 0; kc < 8; kc++) {
            qf[kc][0] = tf32_bits(Qb[(size_t)g       * INNER + kc * 8 + t]);
            qf[kc][1] = tf32_bits(Qb[(size_t)(g + 8) * INNER + kc * 8 + t]);
            qf[kc][2] = tf32_bits(Qb[(size_t)g       * INNER + kc * 8 + t + 4]);
            qf[kc][3] = tf32_bits(Qb[(size_t)(g + 8) * INNER + kc * 8 + t + 4]);
        }
    }

    float m0 = -1e30f, m1 = -1e30f, l0 = 0.f, l1 = 0.f;
    float o[8][4] = {};

    for (int kb = 0; kb < NKV; kb += 64) {
        // cooperative K/V load, converted to tf32 bits.
        // scalar row-major: GMEM coalesced, smem conflict-free.
        {
            const float* Kg = g_k + (size_t)(b * NKV + kb) * INNER + h * 64;
            const float* Vg = g_v + (size_t)(b * NKV + kb) * INNER + h * 64;
#pragma unroll
            for (int i = 0; i < 16; i++) {
                int idx = tid + (i << 8);       // 0..4095
                int r = idx >> 6, c = idx & 63;
                Ks[r * 68 + c] = tf32_bits(Kg[(size_t)r * INNER + c]);
                Vs[r * 72 + c] = tf32_bits(Vg[(size_t)r * INNER + c]);
            }
        }
        __syncthreads();

        // ---- S = Q @ K^T  (16 x 64 per warp) ----
        float sf[8][4];
#pragma unroll
        for (int ni = 0; ni < 8; ni++)
#pragma unroll
            for (int r = 0; r < 4; r++) sf[ni][r] = 0.f;

#pragma unroll
        for (int kc = 0; kc < 8; kc++) {
#pragma unroll
            for (int ni = 0; ni < 8; ni++) {
                uint32_t bb[2];
                bb[0] = Ks[(ni * 8 + g) * 68 + kc * 8 + t];
                bb[1] = Ks[(ni * 8 + g) * 68 + kc * 8 + t + 4];
                MMA_TF32(sf[ni], qf[kc], bb);
            }
        }

        // ---- online softmax (rows g and g+8) ----
        float tm0 = -1e30f, tm1 = -1e30f;
#pragma unroll
        for (int ni = 0; ni < 8; ni++) {
            tm0 = fmaxf(tm0, fmaxf(sf[ni][0], sf[ni][1]));
            tm1 = fmaxf(tm1, fmaxf(sf[ni][2], sf[ni][3]));
        }
        tm0 = fmaxf(tm0, __shfl_xor_sync(0xFFFFFFFF, tm0, 1));
        tm0 = fmaxf(tm0, __shfl_xor_sync(0xFFFFFFFF, tm0, 2));
        tm1 = fmaxf(tm1, __shfl_xor_sync(0xFFFFFFFF, tm1, 1));
        tm1 = fmaxf(tm1, __shfl_xor_sync(0xFFFFFFFF, tm1, 2));

        float mn0 = fmaxf(m0, tm0), mn1 = fmaxf(m1, tm1);
        float a0 = __expf(m0 - mn0), a1 = __expf(m1 - mn1);
        m0 = mn0; m1 = mn1;

        float ps0 = 0.f, ps1 = 0.f;
#pragma unroll
        for (int ni = 0; ni < 8; ni++) {
            sf[ni][0] = __expf(sf[ni][0] - m0); ps0 += sf[ni][0];
            sf[ni][1] = __expf(sf[ni][1] - m0); ps0 += sf[ni][1];
            sf[ni][2] = __expf(sf[ni][2] - m1); ps1 += sf[ni][2];
            sf[ni][3] = __expf(sf[ni][3] - m1); ps1 += sf[ni][3];
        }
        ps0 += __shfl_xor_sync(0xFFFFFFFF, ps0, 1);
        ps0 += __shfl_xor_sync(0xFFFFFFFF, ps0, 2);
        ps1 += __shfl_xor_sync(0xFFFFFFFF, ps1, 1);
        ps1 += __shfl_xor_sync(0xFFFFFFFF, ps1, 2);
        l0 = l0 * a0 + ps0;
        l1 = l1 * a1 + ps1;

        // rescale O accumulators
#pragma unroll
        for (int s = 0; s < 8; s++) {
            o[s][0] *= a0; o[s][1] *= a0;
            o[s][2] *= a1; o[s][3] *= a1;
        }

        // ---- write P (tf32) to per-warp smem ----
        __syncwarp();   // all lanes done reading Pm from previous iteration
#pragma unroll
        for (int ni = 0; ni < 8; ni++) {
            Pm[g * 68 + ni * 8 + t * 2]           = tf32_bits(sf[ni][0]);
            Pm[g * 68 + ni * 8 + t * 2 + 1]       = tf32_bits(sf[ni][1]);
            Pm[(g + 8) * 68 + ni * 8 + t * 2]     = tf32_bits(sf[ni][2]);
            Pm[(g + 8) * 68 + ni * 8 + t * 2 + 1] = tf32_bits(sf[ni][3]);
        }
        __syncwarp();

        // ---- O += P @ V ----
#pragma unroll
        for (int kc = 0; kc < 8; kc++) {
            uint32_t pa[4];
            pa[0] = Pm[g * 68 + kc * 8 + t];
            pa[1] = Pm[(g + 8) * 68 + kc * 8 + t];
            pa[2] = Pm[g * 68 + kc * 8 + t + 4];
            pa[3] = Pm[(g + 8) * 68 + kc * 8 + t + 4];
#pragma unroll
            for (int s = 0; s < 8; s++) {
                uint32_t bb[2];
                bb[0] = Vs[(kc * 8 + t) * 72 + s * 8 + g];
                bb[1] = Vs[(kc * 8 + t + 4) * 72 + s * 8 + g];
                MMA_TF32(o[s], pa, bb);
            }
        }
        __syncthreads();   // protect Ks/Vs for next tile
    }

    // ---- normalize and write out ----
    const float inv0 = 1.f / l0, inv1 = 1.f / l1;
    const int row0 = b * NQ + qb + warp * 16 + g;
#pragma unroll
    for (int s = 0; s < 8; s++) {
        const int col = h * 64 + s * 8 + t * 2;
        float2 w0, w1;
        w0.x = o[s][0] * inv0; w0.y = o[s][1] * inv0;
        w1.x = o[s][2] * inv1; w1.y = o[s][3] * inv1;
        *(float2*)&g_ao[(size_t)row0 * INNER + col]       = w0;
        *(float2*)&g_ao[(size_t)(row0 + 8) * INNER + col] = w1;
    }
}

// ---------------------------------------------------------------------------
extern "C" void kernel_launch(void* const* d_in, const int* in_sizes, int n_in,
                              void* d_out, int out_size)
{
    const float* x   = (const float*)d_in[0];  // [4,2048,512]
    const float* ctx = (const float*)d_in[1];  // [4,2048,768]
    const float* Wq  = (const float*)d_in[2];  // [512,512]
    const float* Wk  = (const float*)d_in[3];  // [512,768]
    const float* Wv  = (const float*)d_in[4];  // [512,768]
    const float* Wo  = (const float*)d_in[5];  // [512,512]
    const float* bo  = (const float*)d_in[6];  // [512]
    float* out = (float*)d_out;

    float *qp, *kp, *vp, *ap;
    cudaGetSymbolAddress((void**)&qp, g_q);
    cudaGetSymbolAddress((void**)&kp, g_k);
    cudaGetSymbolAddress((void**)&vp, g_v);
    cudaGetSymbolAddress((void**)&ap, g_ao);

    dim3 gProj(INNER / 128, ROWS / 128);   // (4, 64)

    // Q = x @ Wq^T * SCALE ; K = ctx @ Wk^T ; V = ctx @ Wv^T
    gemm_mma<<<gProj, 256>>>(x,   Wq, nullptr, qp, ROWS, INNER, QDIM, SCALE);
    gemm_mma<<<gProj, 256>>>(ctx, Wk, nullptr, kp, ROWS, INNER, CDIM, 1.0f);
    gemm_mma<<<gProj, 256>>>(ctx, Wv, nullptr, vp, ROWS, INNER, CDIM, 1.0f);

    cudaFuncSetAttribute(attn_mma,
                         cudaFuncAttributeMaxDynamicSharedMemorySize,
                         A2_SMEM_BYTES);
    attn_mma<<<dim3(NQ / 128, HEADS, BATCH), 256, A2_SMEM_BYTES>>>();

    // out = attn_out @ Wo^T + bo
    gemm_mma<<<dim3(QDIM / 128, ROWS / 128), 256>>>(ap, Wo, bo, out,
                                                    ROWS, QDIM, INNER, 1.0f);
}

// round 9
// speedup vs baseline: 1.9327x; 1.5716x over previous
#include <cuda_runtime.h>
#include <cstdint>
#include <cstddef>

#define HEADS    8
#define DIM_HEAD 64
#define QDIM     512
#define CDIM     768
#define INNER    512
#define BATCH    4
#define NQ       2048
#define NKV      2048
#define ROWS     (BATCH * NQ)   // 8192
#define SCALE    0.125f         // 64^-0.5

// Scratch (allocation-free rule: device globals)
__device__ float g_q[ROWS * INNER];
__device__ float g_k[ROWS * INNER];
__device__ float g_v[ROWS * INNER];
__device__ float g_ao[ROWS * INNER];

// ===========================================================================
// Warp-MMA tf32 helpers (baseline PTX, no sm_103a-only instructions)
// ===========================================================================
__device__ __forceinline__ uint32_t tf32_bits(float x) {
    uint32_t r;
    asm("cvt.rna.tf32.f32 %0, %1;" : "=r"(r) : "f"(x));
    return r;
}

__device__ __forceinline__ void tf32_split(float x, uint32_t& hi, uint32_t& lo) {
    hi = tf32_bits(x);
    lo = tf32_bits(x - __uint_as_float(hi));
}

#define MMA_TF32(d, a, b)                                                     \
    asm volatile(                                                             \
        "mma.sync.aligned.m16n8k8.row.col.f32.tf32.tf32.f32 "                 \
        "{%0,%1,%2,%3}, {%4,%5,%6,%7}, {%8,%9}, {%0,%1,%2,%3};"               \
        : "+f"((d)[0]), "+f"((d)[1]), "+f"((d)[2]), "+f"((d)[3])              \
        : "r"((a)[0]), "r"((a)[1]), "r"((a)[2]), "r"((a)[3]),                 \
          "r"((b)[0]), "r"((b)[1]))

// ===========================================================================
// 3xTF32 NT GEMM: C = scale*(A @ B^T) + bias.  128x128 CTA tile, BK=16,
// 256 threads = 8 warps (2x4), warp tile 64x32.  tf32 split hoisted to the
// load stage (hi/lo smem copies) with VECTORIZED uint4 stores.
// ===========================================================================
__global__ __launch_bounds__(256)
void gemm_mma(const float* __restrict__ A, const float* __restrict__ Bw,
              const float* __restrict__ bias, float* __restrict__ C,
              int M, int ldc, int K, float scale)
{
    __shared__ uint32_t Ah[128][20], Al[128][20];
    __shared__ uint32_t Bh[128][20], Bl[128][20];

    const int tid    = threadIdx.x;
    const int warp   = tid >> 5;
    const int lane   = tid & 31;
    const int gid    = lane >> 2;       // 0..7
    const int tig    = lane & 3;        // 0..3
    const int warp_m = warp & 1;
    const int warp_n = warp >> 1;
    const int mBase  = blockIdx.y << 7;
    const int nBase  = blockIdx.x << 7;

    const int lrow = tid >> 2;          // 0..63
    const int lk4  = (tid & 3) << 2;    // 0,4,8,12

    float acc[4][4][4] = {};

    for (int k0 = 0; k0 < K; k0 += 16) {
#pragma unroll
        for (int r = 0; r < 128; r += 64) {
            float4 av = *(const float4*)&A [(size_t)(mBase + lrow + r) * K + k0 + lk4];
            float4 bv = *(const float4*)&Bw[(size_t)(nBase + lrow + r) * K + k0 + lk4];
            uint4 h, l;
            tf32_split(av.x, h.x, l.x); tf32_split(av.y, h.y, l.y);
            tf32_split(av.z, h.z, l.z); tf32_split(av.w, h.w, l.w);
            *(uint4*)&Ah[lrow + r][lk4] = h;
            *(uint4*)&Al[lrow + r][lk4] = l;
            tf32_split(bv.x, h.x, l.x); tf32_split(bv.y, h.y, l.y);
            tf32_split(bv.z, h.z, l.z); tf32_split(bv.w, h.w, l.w);
            *(uint4*)&Bh[lrow + r][lk4] = h;
            *(uint4*)&Bl[lrow + r][lk4] = l;
        }
        __syncthreads();

#pragma unroll
        for (int ks = 0; ks < 16; ks += 8) {
            uint32_t bh[4][2], bl[4][2];
#pragma unroll
            for (int ni = 0; ni < 4; ni++) {
                const int col = warp_n * 32 + ni * 8 + gid;
                bh[ni][0] = Bh[col][ks + tig];     bl[ni][0] = Bl[col][ks + tig];
                bh[ni][1] = Bh[col][ks + tig + 4]; bl[ni][1] = Bl[col][ks + tig + 4];
            }
#pragma unroll
            for (int mi = 0; mi < 4; mi++) {
                const int row = warp_m * 64 + mi * 16 + gid;
                uint32_t ah[4], al[4];
                ah[0] = Ah[row][ks + tig];         al[0] = Al[row][ks + tig];
                ah[1] = Ah[row + 8][ks + tig];     al[1] = Al[row + 8][ks + tig];
                ah[2] = Ah[row][ks + tig + 4];     al[2] = Al[row][ks + tig + 4];
                ah[3] = Ah[row + 8][ks + tig + 4]; al[3] = Al[row + 8][ks + tig + 4];
#pragma unroll
                for (int ni = 0; ni < 4; ni++) {
                    MMA_TF32(acc[mi][ni], ah, bh[ni]);
                    MMA_TF32(acc[mi][ni], ah, bl[ni]);
                    MMA_TF32(acc[mi][ni], al, bh[ni]);
                }
            }
        }
        __syncthreads();
    }

#pragma unroll
    for (int mi = 0; mi < 4; mi++) {
        const int row0 = mBase + warp_m * 64 + mi * 16 + gid;
#pragma unroll
        for (int ni = 0; ni < 4; ni++) {
            const int col = nBase + warp_n * 32 + ni * 8 + tig * 2;
            float b0 = 0.f, b1 = 0.f;
            if (bias) { b0 = bias[col]; b1 = bias[col + 1]; }
            float2 o0, o1;
            o0.x = acc[mi][ni][0] * scale + b0;
            o0.y = acc[mi][ni][1] * scale + b1;
            o1.x = acc[mi][ni][2] * scale + b0;
            o1.y = acc[mi][ni][3] * scale + b1;
            *(float2*)&C[(size_t)row0 * ldc + col]       = o0;
            *(float2*)&C[(size_t)(row0 + 8) * ldc + col] = o1;
        }
    }
}

// ===========================================================================
// Tensor-core flash attention v2 (tf32 warp MMA).
// CTA = (b, h, 128 q-rows), 256 threads = 8 warps; warp owns 16 q-rows.
// KV tiles of 64.
//  - K stored PAIR-PERMUTED: pos(c) = (c>>3)*8 + (c&3)*2 + ((c&7)>>2) so each
//    B-fragment pair (k, k+4) is one LDS.64.  Stride 72: conflict-free.
//  - P never touches smem: C-frag -> A-frag via lane shuffles.
//  - V natural row-major [key][d], stride 72 (banks 8t+g: conflict-free).
// ===========================================================================
__global__ __launch_bounds__(256, 2)
void attn_mma()
{
    __shared__ uint32_t Ksf[64 * 72];
    __shared__ uint32_t Vs [64 * 72];

    const int tid  = threadIdx.x;
    const int warp = tid >> 5;
    const int lane = tid & 31;
    const int g    = lane >> 2;     // 0..7
    const int t    = lane & 3;      // 0..3
    const int qb   = blockIdx.x << 7;
    const int h    = blockIdx.y;
    const int b    = blockIdx.z;

    // Q fragments for this warp's 16 rows (Q pre-scaled by SCALE), tf32, held
    uint32_t qf[8][4];
    {
        const float* Qb = g_q + (size_t)(b * NQ + qb + warp * 16) * INNER + h * 64;
#pragma unroll
        for (int kc = 0; kc < 8; kc++) {
            qf[kc][0] = tf32_bits(Qb[(size_t)g       * INNER + kc * 8 + t]);
            qf[kc][1] = tf32_bits(Qb[(size_t)(g + 8) * INNER + kc * 8 + t]);
            qf[kc][2] = tf32_bits(Qb[(size_t)g       * INNER + kc * 8 + t + 4]);
            qf[kc][3] = tf32_bits(Qb[(size_t)(g + 8) * INNER + kc * 8 + t + 4]);
        }
    }

    float m0 = -1e30f, m1 = -1e30f, l0 = 0.f, l1 = 0.f;
    float o[8][4] = {};

    const int shsrc0 = (g << 2) + (t >> 1);   // P source lane for cols t
    const int shsrc1 = shsrc0 + 2;            // P source lane for cols t+4
    const bool todd  = (t & 1);

    for (int kb = 0; kb < NKV; kb += 64) {
        // ---- cooperative K/V load (float4 LDG), cvt to tf32 ----
        {
            const float* Kg = g_k + (size_t)(b * NKV + kb) * INNER + h * 64;
            const float* Vg = g_v + (size_t)(b * NKV + kb) * INNER + h * 64;
#pragma unroll
            for (int i = 0; i < 4; i++) {
                int idx = tid + (i << 8);          // 0..1023
                int r   = idx >> 4;                // 0..63
                int c4  = (idx & 15) << 2;         // 0..60
                float4 kv = *(const float4*)&Kg[(size_t)r * INNER + c4];
                // pos(c4+j) = (c4>>3)*8 + j*2 + ((c4&7)>>2)   (c4 4-aligned)
                int base = r * 72 + ((c4 >> 3) << 3) + ((c4 & 7) >> 2);
                Ksf[base + 0] = tf32_bits(kv.x);
                Ksf[base + 2] = tf32_bits(kv.y);
                Ksf[base + 4] = tf32_bits(kv.z);
                Ksf[base + 6] = tf32_bits(kv.w);
                float4 vv = *(const float4*)&Vg[(size_t)r * INNER + c4];
                uint4 vb;
                vb.x = tf32_bits(vv.x); vb.y = tf32_bits(vv.y);
                vb.z = tf32_bits(vv.z); vb.w = tf32_bits(vv.w);
                *(uint4*)&Vs[r * 72 + c4] = vb;
            }
        }
        __syncthreads();

        // ---- S = Q @ K^T  (16 x 64 per warp), paired LDS.64 B-frags ----
        float sf[8][4];
#pragma unroll
        for (int ni = 0; ni < 8; ni++)
#pragma unroll
            for (int r = 0; r < 4; r++) sf[ni][r] = 0.f;

#pragma unroll
        for (int kc = 0; kc < 8; kc++) {
#pragma unroll
            for (int ni = 0; ni < 8; ni++) {
                uint2 bp = *(const uint2*)&Ksf[(ni * 8 + g) * 72 + kc * 8 + t * 2];
                uint32_t bb[2] = {bp.x, bp.y};
                MMA_TF32(sf[ni], qf[kc], bb);
            }
        }

        // ---- online softmax (rows g and g+8) ----
        float tm0 = -1e30f, tm1 = -1e30f;
#pragma unroll
        for (int ni = 0; ni < 8; ni++) {
            tm0 = fmaxf(tm0, fmaxf(sf[ni][0], sf[ni][1]));
            tm1 = fmaxf(tm1, fmaxf(sf[ni][2], sf[ni][3]));
        }
        tm0 = fmaxf(tm0, __shfl_xor_sync(0xFFFFFFFF, tm0, 1));
        tm0 = fmaxf(tm0, __shfl_xor_sync(0xFFFFFFFF, tm0, 2));
        tm1 = fmaxf(tm1, __shfl_xor_sync(0xFFFFFFFF, tm1, 1));
        tm1 = fmaxf(tm1, __shfl_xor_sync(0xFFFFFFFF, tm1, 2));

        float mn0 = fmaxf(m0, tm0), mn1 = fmaxf(m1, tm1);
        float a0 = __expf(m0 - mn0), a1 = __expf(m1 - mn1);
        m0 = mn0; m1 = mn1;

        float ps0 = 0.f, ps1 = 0.f;
        uint32_t pb[8][4];               // P as tf32 bits (c-frag layout)
#pragma unroll
        for (int ni = 0; ni < 8; ni++) {
            float e0 = __expf(sf[ni][0] - m0); ps0 += e0;
            float e1 = __expf(sf[ni][1] - m0); ps0 += e1;
            float e2 = __expf(sf[ni][2] - m1); ps1 += e2;
            float e3 = __expf(sf[ni][3] - m1); ps1 += e3;
            pb[ni][0] = tf32_bits(e0); pb[ni][1] = tf32_bits(e1);
            pb[ni][2] = tf32_bits(e2); pb[ni][3] = tf32_bits(e3);
        }
        ps0 += __shfl_xor_sync(0xFFFFFFFF, ps0, 1);
        ps0 += __shfl_xor_sync(0xFFFFFFFF, ps0, 2);
        ps1 += __shfl_xor_sync(0xFFFFFFFF, ps1, 1);
        ps1 += __shfl_xor_sync(0xFFFFFFFF, ps1, 2);
        l0 = l0 * a0 + ps0;
        l1 = l1 * a1 + ps1;

#pragma unroll
        for (int s = 0; s < 8; s++) {
            o[s][0] *= a0; o[s][1] *= a0;
            o[s][2] *= a1; o[s][3] *= a1;
        }

        // ---- O += P @ V : A-frag of P via shuffles, no smem ----
#pragma unroll
        for (int kc = 0; kc < 8; kc++) {
            uint32_t r0  = __shfl_sync(0xFFFFFFFF, pb[kc][0], shsrc0);
            uint32_t r1  = __shfl_sync(0xFFFFFFFF, pb[kc][1], shsrc0);
            uint32_t r2  = __shfl_sync(0xFFFFFFFF, pb[kc][2], shsrc0);
            uint32_t r3  = __shfl_sync(0xFFFFFFFF, pb[kc][3], shsrc0);
            uint32_t r0b = __shfl_sync(0xFFFFFFFF, pb[kc][0], shsrc1);
            uint32_t r1b = __shfl_sync(0xFFFFFFFF, pb[kc][1], shsrc1);
            uint32_t r2b = __shfl_sync(0xFFFFFFFF, pb[kc][2], shsrc1);
            uint32_t r3b = __shfl_sync(0xFFFFFFFF, pb[kc][3], shsrc1);
            uint32_t pa[4];
            pa[0] = todd ? r1  : r0;    // P[g   ][kc*8+t]
            pa[1] = todd ? r3  : r2;    // P[g+8 ][kc*8+t]
            pa[2] = todd ? r1b : r0b;   // P[g   ][kc*8+t+4]
            pa[3] = todd ? r3b : r2b;   // P[g+8 ][kc*8+t+4]
#pragma unroll
            for (int s = 0; s < 8; s++) {
                uint32_t bb[2];
                bb[0] = Vs[(kc * 8 + t) * 72 + s * 8 + g];
                bb[1] = Vs[(kc * 8 + t + 4) * 72 + s * 8 + g];
                MMA_TF32(o[s], pa, bb);
            }
        }
        __syncthreads();   // protect Ksf/Vs for next tile
    }

    // ---- normalize and write out ----
    const float inv0 = 1.f / l0, inv1 = 1.f / l1;
    const int row0 = b * NQ + qb + warp * 16 + g;
#pragma unroll
    for (int s = 0; s < 8; s++) {
        const int col = h * 64 + s * 8 + t * 2;
        float2 w0, w1;
        w0.x = o[s][0] * inv0; w0.y = o[s][1] * inv0;
        w1.x = o[s][2] * inv1; w1.y = o[s][3] * inv1;
        *(float2*)&g_ao[(size_t)row0 * INNER + col]       = w0;
        *(float2*)&g_ao[(size_t)(row0 + 8) * INNER + col] = w1;
    }
}

// ---------------------------------------------------------------------------
extern "C" void kernel_launch(void* const* d_in, const int* in_sizes, int n_in,
                              void* d_out, int out_size)
{
    const float* x   = (const float*)d_in[0];  // [4,2048,512]
    const float* ctx = (const float*)d_in[1];  // [4,2048,768]
    const float* Wq  = (const float*)d_in[2];  // [512,512]
    const float* Wk  = (const float*)d_in[3];  // [512,768]
    const float* Wv  = (const float*)d_in[4];  // [512,768]
    const float* Wo  = (const float*)d_in[5];  // [512,512]
    const float* bo  = (const float*)d_in[6];  // [512]
    float* out = (float*)d_out;

    float *qp, *kp, *vp, *ap;
    cudaGetSymbolAddress((void**)&qp, g_q);
    cudaGetSymbolAddress((void**)&kp, g_k);
    cudaGetSymbolAddress((void**)&vp, g_v);
    cudaGetSymbolAddress((void**)&ap, g_ao);

    dim3 gProj(INNER / 128, ROWS / 128);   // (4, 64)

    // Q = x @ Wq^T * SCALE ; K = ctx @ Wk^T ; V = ctx @ Wv^T
    gemm_mma<<<gProj, 256>>>(x,   Wq, nullptr, qp, ROWS, INNER, QDIM, SCALE);
    gemm_mma<<<gProj, 256>>>(ctx, Wk, nullptr, kp, ROWS, INNER, CDIM, 1.0f);
    gemm_mma<<<gProj, 256>>>(ctx, Wv, nullptr, vp, ROWS, INNER, CDIM, 1.0f);

    attn_mma<<<dim3(NQ / 128, HEADS, BATCH), 256>>>();

    // out = attn_out @ Wo^T + bo
    gemm_mma<<<dim3(QDIM / 128, ROWS / 128), 256>>>(ap, Wo, bo, out,
                                                    ROWS, QDIM, INNER, 1.0f);
}